// round 6
// baseline (speedup 1.0000x reference)
#include <cuda_runtime.h>
#include <cstdint>

#define SA 20        // alphabet
#define HH 2
#define KK 2
#define NM 4         // H*K matrices
#define LL 512
#define BB 1024
#define NRATES 100000
#define NSWEEP 5
#define BPB 4        // blocks per batch item in anc kernel
#define PPB 256      // positions per anc block

// persistent scratch (allocation-free rule: __device__ globals)
__device__ float g_U[NM][SA][SA];
__device__ float g_lam[NM][SA];
__device__ float g_sp[NM][SA];
__device__ float g_isp[NM][SA];

__device__ __forceinline__ float softplusf(float x) {
    return fmaxf(x, 0.f) + log1pf(expf(-fabsf(x)));
}

// ---------------- Kernel A: build Sm per (h,k) and Jacobi-diagonalize ----------------
// 128 threads per block (4 warps): cheap barriers. Double-buffered single-phase
// update: A' = J^T A J element-wise from the OLD buffer:
//   A'[i][j] = ci*(cj*a00 + sj*a01) + si*(cj*a10 + sj*a11)
__global__ __launch_bounds__(128, 1)
void eig_kernel(const float* __restrict__ exch, const float* __restrict__ equil) {
    __shared__ float A[2][SA][SA + 1];
    __shared__ float Ut[2][SA][SA + 1];
    __shared__ float cc[SA], ssg[SA];
    __shared__ int   part[SA];
    __shared__ float pvec[SA], spv[SA], ispv[SA], rowv[SA];
    __shared__ float inv_mue;

    const int m = blockIdx.x;     // m = h*KK + k
    const int t = threadIdx.x;

    // equilibrium softmax (serial, trivial)
    if (t == 0) {
        float mx = -1e30f;
        for (int s = 0; s < SA; s++) mx = fmaxf(mx, equil[m * SA + s]);
        float e[SA], sum = 0.f;
        for (int s = 0; s < SA; s++) { e[s] = expf(equil[m * SA + s] - mx); sum += e[s]; }
        float inv = 1.f / sum;
        for (int s = 0; s < SA; s++) {
            float ps = e[s] * inv;
            pvec[s] = ps;
            float sq = sqrtf(ps);
            spv[s] = sq;
            ispv[s] = 1.f / sq;
        }
    }
    __syncthreads();

    // Q_ij (pre-diagonal) = softplus(0.5*(Kij+Kji)) * (i!=j) * p_j   -> A[0]
    for (int e = t; e < SA * SA; e += 128) {
        int i = e / SA, j = e % SA;
        float kij = exch[m * SA * SA + i * SA + j];
        float kji = exch[m * SA * SA + j * SA + i];
        float r = (i == j) ? 0.f : softplusf(0.5f * (kij + kji));
        A[0][i][j] = r * pvec[j];
    }
    __syncthreads();
    if (t < SA) { float s = 0.f; for (int j = 0; j < SA; j++) s += A[0][t][j]; rowv[t] = s; }
    __syncthreads();
    if (t == 0) {
        float mue = 0.f;
        for (int i = 0; i < SA; i++) mue += pvec[i] * rowv[i];
        inv_mue = 1.f / fmaxf(mue, 1e-16f);
    }
    __syncthreads();
    // Sm into A[1] (temp)
    for (int e = t; e < SA * SA; e += 128) {
        int i = e / SA, j = e % SA;
        float q = (A[0][i][j] - ((i == j) ? rowv[i] : 0.f)) * inv_mue;
        A[1][i][j] = spv[i] * q * ispv[j];
    }
    __syncthreads();
    // symmetrize into A[0]; init U = I
    for (int e = t; e < SA * SA; e += 128) {
        int i = e / SA, j = e % SA;
        A[0][i][j] = 0.5f * (A[1][i][j] + A[1][j][i]);
        Ut[0][i][j] = (i == j) ? 1.f : 0.f;
    }

    int cur = 0;
    for (int round = 0; round < NSWEEP * (SA - 1); round++) {
        int r = round % (SA - 1);
        __syncthreads();
        if (t < SA / 2) {
            int k = t;
            int posa = k, posb = SA - 1 - k;
            int P_ = (posa == 0) ? 0 : 1 + (posa - 1 + r) % (SA - 1);
            int Q_ = 1 + (posb - 1 + r) % (SA - 1);
            float app = A[cur][P_][P_], aqq = A[cur][Q_][Q_], apq = A[cur][P_][Q_];
            float c = 1.f, s = 0.f;
            if (fabsf(apq) > 1e-13f) {
                float theta = (aqq - app) / (2.f * apq);
                float tt = copysignf(1.f, theta) / (fabsf(theta) + sqrtf(theta * theta + 1.f));
                c = rsqrtf(tt * tt + 1.f);
                s = tt * c;
            }
            cc[P_] = c; ssg[P_] = -s; part[P_] = Q_;
            cc[Q_] = c; ssg[Q_] =  s; part[Q_] = P_;
        }
        __syncthreads();
        for (int e = t; e < SA * SA; e += 128) {
            int i = e / SA, j = e % SA;
            int pi = part[i], pj = part[j];
            float ci = cc[i], si = ssg[i];
            float cj = cc[j], sj = ssg[j];
            float a00 = A[cur][i][j],  a01 = A[cur][i][pj];
            float a10 = A[cur][pi][j], a11 = A[cur][pi][pj];
            A[cur ^ 1][i][j] = ci * (cj * a00 + sj * a01) + si * (cj * a10 + sj * a11);
            float u0 = Ut[cur][i][j], u1 = Ut[cur][i][pj];
            Ut[cur ^ 1][i][j] = cj * u0 + sj * u1;
        }
        cur ^= 1;
    }
    __syncthreads();
    for (int e = t; e < SA * SA; e += 128) {
        int i = e / SA, j = e % SA;
        g_U[m][i][j] = Ut[cur][i][j];
    }
    if (t < SA) {
        g_lam[m][t] = A[cur][t][t];
        g_sp[m][t]  = spv[t];
        g_isp[m][t] = ispv[t];
    }
}

// ---------------- Kernel B: per-block P reconstruction + fully-coalesced gather ----------------
// 4 blocks per batch item, 256 threads, 256 contiguous positions per block.
// Phase 1: coalesced one-hot scan -> z table in smem.
// Phase 2: coalesced output write (each warp's STG.128 covers 512 contiguous bytes).
__global__ __launch_bounds__(256, 8)
void anc_kernel(const float* __restrict__ inputs, const int* __restrict__ ridx,
                const float* __restrict__ tauk, float* __restrict__ out) {
    __shared__ __align__(16) float Pm[NM][SA][SA];   // Pm[h*KK+k][z][s]
    __shared__ __align__(16) float Us[NM][SA][SA];
    __shared__ __align__(16) float Vs[NM][SA][SA];
    __shared__ float w[NM][SA];
    __shared__ float sps[NM][SA], isps[NM][SA];
    __shared__ float tau[HH];
    __shared__ int   zsh[PPB];

    const int b = blockIdx.x / BPB;
    const int q = blockIdx.x % BPB;
    const int t = threadIdx.x;

    if (t < HH) {
        int idx = ridx[b * HH + t];
        tau[t] = softplusf(tauk[t * NRATES + idx]);
    }
    __syncthreads();
    if (t < NM * SA) {
        int m = t / SA, s = t % SA;
        int h = m / KK;
        w[m][s]    = expf(tau[h] * g_lam[m][s]);
        sps[m][s]  = g_sp[m][s];
        isps[m][s] = g_isp[m][s];
    }
    __syncthreads();
    for (int e = t; e < NM * SA * SA; e += blockDim.x) {
        int m = e / (SA * SA);
        int rs = e % (SA * SA);
        int j = rs / SA, s = rs % SA;
        float u = g_U[m][j][s];
        Us[m][j][s] = u;
        Vs[m][j][s] = u * w[m][s];
    }
    __syncthreads();
    for (int e = t; e < NM * SA * SA; e += blockDim.x) {
        int m = e / (SA * SA);
        int rs = e % (SA * SA);
        int i = rs / SA, j = rs % SA;
        float acc = 0.f;
#pragma unroll
        for (int s = 0; s < SA; s++) acc += Us[m][i][s] * Vs[m][j][s];
        Pm[m][i][j] = isps[m][i] * acc * sps[m][j];
    }

    // ---- Phase 1: one-hot scan (coalesced). Block input span = PPB*20 floats. ----
    const int POS = LL * HH;                               // 1024 positions per b
    const size_t posbase = (size_t)b * POS + (size_t)q * PPB;
    const float4* ip = (const float4*)(inputs + posbase * SA);   // 1280 float4s
    for (int i = 0; i < 5; i++) {
        int g4 = t + i * PPB;          // float4 index, coalesced
        float4 v = ip[g4];
        int e0 = g4 * 4;
        if (v.x > 0.5f) { int e = e0 + 0; zsh[e / SA] = e % SA; }
        if (v.y > 0.5f) { int e = e0 + 1; zsh[e / SA] = e % SA; }
        if (v.z > 0.5f) { int e = e0 + 2; zsh[e / SA] = e % SA; }
        if (v.w > 0.5f) { int e = e0 + 3; zsh[e / SA] = e % SA; }
    }
    __syncthreads();

    // ---- Phase 2: coalesced output. Block output span = PPB*40 floats = 2560 float4s. ----
    float4* op = (float4*)(out + posbase * (KK * SA));
    for (int i = 0; i < 10; i++) {
        int g = t + i * PPB;           // float4 index, coalesced
        int pos_local = g / 10;
        int elem = g - pos_local * 10; // 0..9
        int h = pos_local & 1;         // q*PPB even -> parity preserved
        int k = (elem >= 5) ? 1 : 0;
        int c4 = elem - k * 5;
        int z = zsh[pos_local];
        int mi = h * KK + k;
        float4 v = *(const float4*)&Pm[mi][z][c4 * 4];
        op[g] = v;
    }
}

extern "C" void kernel_launch(void* const* d_in, const int* in_sizes, int n_in,
                              void* d_out, int out_size) {
    const float* inputs = (const float*)d_in[0];   // (B,L,H,20) f32
    const int*   ridx   = (const int*)d_in[1];     // (B,H) i32
    const float* tauk   = (const float*)d_in[2];   // (H,NUM_RATES) f32
    const float* exch   = (const float*)d_in[3];   // (H,K,20,20) f32
    const float* equil  = (const float*)d_in[4];   // (H,K,20) f32
    float* out = (float*)d_out;                    // (B,L,H,K,20) f32

    eig_kernel<<<NM, 128>>>(exch, equil);
    anc_kernel<<<BB * BPB, 256>>>(inputs, ridx, tauk, out);
}

// round 7
// speedup vs baseline: 2.3802x; 2.3802x over previous
#include <cuda_runtime.h>
#include <cstdint>

#define SA 20        // alphabet
#define HH 2
#define KK 2
#define NM 4         // H*K matrices
#define LL 512
#define BB 1024
#define NRATES 100000
#define NSWEEP 5
#define NPOS (BB * LL * HH)      // 1,048,576 positions
#define SCANB 2048               // scan blocks in kernel 1 (512 pos each)
#define PPB2 512                 // positions per anc block
#define BPB2 2                   // anc blocks per batch item

// persistent scratch (allocation-free rule: __device__ globals)
__device__ float   g_U[NM][SA][SA];
__device__ float   g_lam[NM][SA];
__device__ float   g_sp[NM][SA];
__device__ float   g_isp[NM][SA];
__device__ unsigned char g_z[NPOS];   // argmax index per position

__device__ __forceinline__ float softplusf(float x) {
    return fmaxf(x, 0.f) + log1pf(expf(-fabsf(x)));
}

// ---------------- Kernel 1: eig (blocks 0..NM-1) + input scan (rest), concurrent ----------------
__global__ __launch_bounds__(512, 2)
void eig_scan_kernel(const float* __restrict__ exch, const float* __restrict__ equil,
                     const float* __restrict__ inputs) {
    __shared__ float Abuf[2][SA][SA + 1];
    __shared__ float Ubuf[2][SA][SA + 1];
    __shared__ __align__(16) float4 tab[SA];
    __shared__ float pvec[SA], spv[SA], ispv[SA], rowv[SA];
    __shared__ float inv_mue;
    __shared__ int   zsh[512];

    const int t = threadIdx.x;

    if (blockIdx.x >= NM) {
        // ================= scan path: one-hot -> z table =================
        const int sb = blockIdx.x - NM;
        const int posbase = sb * 512;                   // 512 positions per block
        const float4* ip = (const float4*)(inputs + (size_t)posbase * SA); // 2560 float4
        int p = t / 5;                 // e0 = 4t ; p = e0/20
        int r = 4 * t - 20 * p;        // e0 % 20
        for (int i = 0; i < 5; i++) {
            float4 v = ip[t + i * 512];
            // components r, r+1, r+2, r+3 (wrap at 20 -> next position)
            float c0 = v.x, c1 = v.y, c2 = v.z, c3 = v.w;
            int rr, pp;
            rr = r;     pp = p;     if (rr >= 20) { rr -= 20; pp += 1; }
            if (c0 > 0.5f) zsh[pp] = rr;
            rr = r + 1; pp = p;     if (rr >= 20) { rr -= 20; pp += 1; }
            if (c1 > 0.5f) zsh[pp] = rr;
            rr = r + 2; pp = p;     if (rr >= 20) { rr -= 20; pp += 1; }
            if (c2 > 0.5f) zsh[pp] = rr;
            rr = r + 3; pp = p;     if (rr >= 20) { rr -= 20; pp += 1; }
            if (c3 > 0.5f) zsh[pp] = rr;
            // advance by 2048 elements = 102*20 + 8
            p += 102; r += 8; if (r >= 20) { r -= 20; p += 1; }
        }
        __syncthreads();
        if (t < 128) {   // pack 4 bytes -> coalesced 512B store
            unsigned int w = (unsigned int)zsh[4 * t]
                           | ((unsigned int)zsh[4 * t + 1] << 8)
                           | ((unsigned int)zsh[4 * t + 2] << 16)
                           | ((unsigned int)zsh[4 * t + 3] << 24);
            ((unsigned int*)(g_z + posbase))[t] = w;
        }
        return;
    }

    // ================= eig path =================
    const int m = blockIdx.x;
    const int i = t / SA, j = t % SA;        // owned element (t < 400)
    const bool act = (t < SA * SA);

    if (t == 0) {
        float mx = -1e30f;
        for (int s = 0; s < SA; s++) mx = fmaxf(mx, equil[m * SA + s]);
        float e[SA], sum = 0.f;
        for (int s = 0; s < SA; s++) { e[s] = expf(equil[m * SA + s] - mx); sum += e[s]; }
        float inv = 1.f / sum;
        for (int s = 0; s < SA; s++) {
            float ps = e[s] * inv;
            pvec[s] = ps;
            float sq = sqrtf(ps);
            spv[s] = sq;
            ispv[s] = 1.f / sq;
        }
    }
    __syncthreads();

    // pre-diagonal Q into Abuf[0]
    if (act) {
        float kij = exch[m * SA * SA + i * SA + j];
        float kji = exch[m * SA * SA + j * SA + i];
        float rr = (i == j) ? 0.f : softplusf(0.5f * (kij + kji));
        Abuf[0][i][j] = rr * pvec[j];
    }
    __syncthreads();
    if (t < SA) { float s = 0.f; for (int jj = 0; jj < SA; jj++) s += Abuf[0][t][jj]; rowv[t] = s; }
    __syncthreads();
    if (t == 0) {
        float mue = 0.f;
        for (int ii = 0; ii < SA; ii++) mue += pvec[ii] * rowv[ii];
        inv_mue = 1.f / fmaxf(mue, 1e-16f);
    }
    __syncthreads();
    if (act) {
        float q = (Abuf[0][i][j] - ((i == j) ? rowv[i] : 0.f)) * inv_mue;
        Abuf[1][i][j] = spv[i] * q * ispv[j];
    }
    __syncthreads();

    float a = 0.f, u = 0.f;
    if (act) {
        a = 0.5f * (Abuf[1][i][j] + Abuf[1][j][i]);   // symmetric Sm element
        u = (i == j) ? 1.f : 0.f;
    }

    for (int round = 0; round < NSWEEP * (SA - 1); round++) {
        const int p = round & 1;
        const int r = round % (SA - 1);
        if (act) { Abuf[p][i][j] = a; Ubuf[p][i][j] = u; }
        __syncthreads();
        if (t < SA / 2) {
            int k = t;
            int posa = k, posb = SA - 1 - k;
            int P_ = (posa == 0) ? 0 : 1 + (posa - 1 + r) % (SA - 1);
            int Q_ = 1 + (posb - 1 + r) % (SA - 1);
            float app = Abuf[p][P_][P_], aqq = Abuf[p][Q_][Q_], apq = Abuf[p][P_][Q_];
            float c = 1.f, s = 0.f;
            if (fabsf(apq) > 1e-13f) {
                float theta = (aqq - app) / (2.f * apq);
                float tt = copysignf(1.f, theta) / (fabsf(theta) + sqrtf(theta * theta + 1.f));
                c = rsqrtf(tt * tt + 1.f);
                s = tt * c;
            }
            tab[P_] = make_float4(c, -s, (float)Q_, 0.f);
            tab[Q_] = make_float4(c,  s, (float)P_, 0.f);
        }
        __syncthreads();
        if (act) {
            float4 ti = tab[i], tj = tab[j];
            int pi = (int)ti.z, pj = (int)tj.z;
            float ci = ti.x, si = ti.y;
            float cj = tj.x, sj = tj.y;
            float a01 = Abuf[p][i][pj];
            float a10 = Abuf[p][pi][j];
            float a11 = Abuf[p][pi][pj];
            float u1  = Ubuf[p][i][pj];
            a = ci * (cj * a + sj * a01) + si * (cj * a10 + sj * a11);
            u = cj * u + sj * u1;
        }
    }

    if (act) {
        g_U[m][i][j] = u;
        if (i == j) g_lam[m][i] = a;
    }
    if (t < SA) {
        g_sp[m][t]  = spv[t];
        g_isp[m][t] = ispv[t];
    }
}

// ---------------- Kernel 2: P reconstruction + pure coalesced write stream ----------------
// 2 blocks per batch item, 256 threads, 512 positions per block. Reads only the
// 1MB z table; writes 168MB coalesced float4. Division-free loop index math.
__global__ __launch_bounds__(256, 8)
void anc_kernel(const int* __restrict__ ridx, const float* __restrict__ tauk,
                float* __restrict__ out) {
    __shared__ __align__(16) float Pm[NM * SA * SA];   // [(h*KK+k)*400 + z*20 + s]
    __shared__ __align__(16) float Us[NM][SA][SA];
    __shared__ __align__(16) float Vs[NM][SA][SA];
    __shared__ float w[NM][SA];
    __shared__ float sps[NM][SA], isps[NM][SA];
    __shared__ float tau[HH];
    __shared__ int   zsh[PPB2];

    const int b = blockIdx.x >> 1;        // BPB2 = 2
    const int q = blockIdx.x & 1;
    const int t = threadIdx.x;
    const int posbase = b * (LL * HH) + q * PPB2;

    // load z slice (512 bytes, coalesced)
    if (t < PPB2 / 4) {
        unsigned int wz = ((const unsigned int*)(g_z + posbase))[t];
        zsh[4 * t]     = wz & 0xff;
        zsh[4 * t + 1] = (wz >> 8) & 0xff;
        zsh[4 * t + 2] = (wz >> 16) & 0xff;
        zsh[4 * t + 3] = (wz >> 24) & 0xff;
    }
    if (t < HH) {
        int idx = ridx[b * HH + t];
        tau[t] = softplusf(tauk[t * NRATES + idx]);
    }
    __syncthreads();
    if (t < NM * SA) {
        int m = t / SA, s = t % SA;
        int h = m / KK;
        w[m][s]    = expf(tau[h] * g_lam[m][s]);
        sps[m][s]  = g_sp[m][s];
        isps[m][s] = g_isp[m][s];
    }
    __syncthreads();
    for (int e = t; e < NM * SA * SA; e += blockDim.x) {
        int m = e / (SA * SA);
        int rs = e % (SA * SA);
        int j = rs / SA, s = rs % SA;
        float uu = g_U[m][j][s];
        Us[m][j][s] = uu;
        Vs[m][j][s] = uu * w[m][s];
    }
    __syncthreads();
    for (int e = t; e < NM * SA * SA; e += blockDim.x) {
        int m = e / (SA * SA);
        int rs = e % (SA * SA);
        int i = rs / SA, j = rs % SA;
        float acc = 0.f;
#pragma unroll
        for (int s = 0; s < SA; s++) acc += Us[m][i][s] * Vs[m][j][s];
        Pm[m * SA * SA + i * SA + j] = isps[m][i] * acc * sps[m][j];
    }
    __syncthreads();

    // coalesced write stream: block span = PPB2*40 floats = 5120 float4s
    float4* op = (float4*)(out + (size_t)posbase * (KK * SA));
    int gp = t / 10;            // position-local of float4 index g = t
    int ge = t - 10 * gp;       // element 0..9 within position
    for (int it = 0; it < 20; it++) {
        int z = zsh[gp];
        int h = gp & 1;                       // posbase even -> parity preserved
        int k = (ge >= 5) ? 1 : 0;
        int off = (h * KK + k) * (SA * SA) + z * SA + (ge - 5 * k) * 4;
        float4 v = *(const float4*)&Pm[off];
        op[t + it * 256] = v;
        // advance g by 256 = 25*10 + 6
        gp += 25; ge += 6; if (ge >= 10) { ge -= 10; gp += 1; }
    }
}

extern "C" void kernel_launch(void* const* d_in, const int* in_sizes, int n_in,
                              void* d_out, int out_size) {
    const float* inputs = (const float*)d_in[0];   // (B,L,H,20) f32
    const int*   ridx   = (const int*)d_in[1];     // (B,H) i32
    const float* tauk   = (const float*)d_in[2];   // (H,NUM_RATES) f32
    const float* exch   = (const float*)d_in[3];   // (H,K,20,20) f32
    const float* equil  = (const float*)d_in[4];   // (H,K,20) f32
    float* out = (float*)d_out;                    // (B,L,H,K,20) f32

    eig_scan_kernel<<<NM + SCANB, 512>>>(exch, equil, inputs);
    anc_kernel<<<BB * BPB2, 256>>>(ridx, tauk, out);
}